// round 9
// baseline (speedup 1.0000x reference)
#include <cuda_runtime.h>
#include <math.h>

typedef unsigned long long u64;
typedef unsigned int u32;

#define CDIM   96
#define NWIN   8192
#define TOKENS (2*64*64*64)
#define QKV_LD 292          // %32==4, 16B-aligned rows
#define S_LD   68
#define XW_LD  100          // %32==4 -> conflict-free mma A-fragment LDS
#define HB_LD  388          // %32==4

// Static device scratch (no allocs allowed)
__device__ float g_scratch[(size_t)TOKENS * CDIM];
// Fragment-packed tf32 weights (u64 = {b0 lo, b1 hi})
__device__ u64 g_wqkvf[2 * 12 * 36 * 32];   // K=96 (KT12), N=288 (NT36)
__device__ u64 g_w1f  [2 * 12 * 48 * 32];   // K=96,  N=384
__device__ u64 g_w2f  [2 * 48 * 12 * 32];   // K=384, N=96
__device__ u64 g_wpf  [2 * 12 * 12 * 32];   // K=96,  N=96 (proj)
// Dense rel-pos bias: [layer][head][q=64][k=64]
__device__ float g_bias[2 * 3 * 64 * 64];

#define ASMEM ((64*XW_LD + 64*QKV_LD + 3*64*S_LD) * 4)
#define MSMEM ((64*XW_LD + 64*HB_LD) * 4)

// ---- tf32 helpers ----
__device__ __forceinline__ u32 tf32bits(float x) {
    u32 r; asm("cvt.rna.tf32.f32 %0,%1;" : "=r"(r) : "f"(x)); return r;
}
__device__ __forceinline__ float tf32r(float x) {
    return __uint_as_float(tf32bits(x));
}
__device__ __forceinline__ void mma_tf32(
    float& c0, float& c1, float& c2, float& c3,
    u32 a0, u32 a1, u32 a2, u32 a3, u32 b0, u32 b1)
{
    asm("mma.sync.aligned.m16n8k8.row.col.f32.tf32.tf32.f32 "
        "{%0,%1,%2,%3},{%4,%5,%6,%7},{%8,%9},{%0,%1,%2,%3};"
        : "+f"(c0), "+f"(c1), "+f"(c2), "+f"(c3)
        : "r"(a0), "r"(a1), "r"(a2), "r"(a3), "r"(b0), "r"(b1));
}

// ---------------------------------------------------------------------------
// Pack row-major W[K][N] (per layer) into mma B-fragment order.
// ---------------------------------------------------------------------------
__global__ void pack_kernel(const float* __restrict__ W, u64* __restrict__ dst,
                            int KT, int NT, int N, int total)
{
    int i = blockIdx.x * blockDim.x + threadIdx.x;
    if (i >= total) return;
    int per_layer = KT * NT * 32;
    int layer = i / per_layer;
    int r = i - layer * per_layer;
    int t = r >> 5, lane = r & 31;
    int kt = t / NT, nt = t - kt * NT;
    int k = kt * 8 + (lane & 3);
    int n = nt * 8 + (lane >> 2);
    const float* Wl = W + (size_t)layer * (KT * 8) * N;
    u32 lo = tf32bits(Wl[(size_t)k * N + n]);
    u32 hi = tf32bits(Wl[(size_t)(k + 4) * N + n]);
    dst[i] = ((u64)hi << 32) | lo;
}

// ---------------------------------------------------------------------------
// Precompute dense rel-pos bias matrices (window-invariant).
// ---------------------------------------------------------------------------
__global__ void bias_kernel(const float* __restrict__ tb) {
    int i = blockIdx.x * blockDim.x + threadIdx.x;
    if (i >= 2*3*64*64) return;
    int layer = i / (3*4096);
    int r = i % (3*4096);
    int h = r / 4096;
    int qk = r & 4095;
    int q = qk >> 6, k = qk & 63;
    int qd = q >> 4, qh = (q >> 2) & 3, qw = q & 3;
    int kd = k >> 4, kh = (k >> 2) & 3, kw = k & 3;
    int ridx = (qd-kd+3)*49 + (qh-kh+3)*7 + (qw-kw+3);
    g_bias[i] = tb[layer*1029 + ridx*3 + h];
}

// ---------------------------------------------------------------------------
// Attention block, all GEMMs on tensor cores.
// One CTA per 4x4x4 window, 512 threads (16 warps: mt=warp&3, ng=warp>>2).
// ---------------------------------------------------------------------------
__global__ __launch_bounds__(512, 1) void attn_kernel(
    const float* __restrict__ x, float* __restrict__ out,
    const u64*  __restrict__ Wqkvf, const float* __restrict__ Bqkv,
    const u64*  __restrict__ Wpf,   const float* __restrict__ Bp,
    const float* __restrict__ biasM,
    const float* __restrict__ g1,   const float* __restrict__ b1,
    int shift)
{
    extern __shared__ float sm[];
    float* xw  = sm;                    // 64 x XW_LD; later aliased as ao
    float* qkv = xw + 64*XW_LD;         // 64 x 292 (tf32-rounded)
    float* S3  = qkv + 64*QKV_LD;       // 3 x 64 x 68
    float* ao  = xw;

    const int tid  = threadIdx.x;
    const int lane = tid & 31;
    const int warp = tid >> 5;
    const int mt   = warp & 3;
    const int ng   = warp >> 2;
    const int gid  = lane >> 2;
    const int tig  = lane & 3;

    const int bw   = blockIdx.x;
    const int b    = bw >> 12;
    const int widx = bw & 4095;
    const int wd   = widx >> 8;
    const int wh   = (widx >> 4) & 15;
    const int ww   = widx & 15;

    // ---- LN1 (one warp per token), store tf32-rounded ----
    for (int t = warp; t < 64; t += 16) {
        int td = t >> 4, th = (t >> 2) & 3, tw = t & 3;
        int gd = (wd*4 + td + shift) & 63;
        int gh = (wh*4 + th + shift) & 63;
        int gw = (ww*4 + tw + shift) & 63;
        const float* src = x + (size_t)((((b*64 + gd)*64 + gh)*64 + gw)) * 96;
        float v0 = src[lane], v1 = src[lane+32], v2 = src[lane+64];
        float s  = v0 + v1 + v2;
        float sq = v0*v0 + v1*v1 + v2*v2;
        #pragma unroll
        for (int o = 16; o; o >>= 1) {
            s  += __shfl_xor_sync(0xffffffffu, s,  o);
            sq += __shfl_xor_sync(0xffffffffu, sq, o);
        }
        float mean = s * (1.0f/96.0f);
        float var  = sq * (1.0f/96.0f) - mean*mean;
        float rstd = rsqrtf(var + 1e-5f);
        xw[t*XW_LD+lane]    = tf32r((v0-mean)*rstd*g1[lane]    + b1[lane]);
        xw[t*XW_LD+lane+32] = tf32r((v1-mean)*rstd*g1[lane+32] + b1[lane+32]);
        xw[t*XW_LD+lane+64] = tf32r((v2-mean)*rstd*g1[lane+64] + b1[lane+64]);
    }
    __syncthreads();

    // ---- QKV GEMM (MMA): 9 n-tiles per warp; outputs tf32-rounded, q scaled ----
    {
        float acc[9][4];
        #pragma unroll
        for (int nt = 0; nt < 9; nt++) {
            int col0 = 72*ng + 8*nt + 2*tig;
            float2 bb = *(const float2*)&Bqkv[col0];
            acc[nt][0] = bb.x; acc[nt][1] = bb.y;
            acc[nt][2] = bb.x; acc[nt][3] = bb.y;
        }
        #pragma unroll
        for (int kt = 0; kt < 12; kt++) {
            const float* arow0 = &xw[(16*mt + gid)*XW_LD + 8*kt];
            const float* arow1 = arow0 + 8*XW_LD;
            u32 a0 = __float_as_uint(arow0[tig]);
            u32 a1 = __float_as_uint(arow1[tig]);
            u32 a2 = __float_as_uint(arow0[tig+4]);
            u32 a3 = __float_as_uint(arow1[tig+4]);
            #pragma unroll
            for (int nt = 0; nt < 9; nt++) {
                u64 w = Wqkvf[(kt*36 + ng*9 + nt)*32 + lane];
                mma_tf32(acc[nt][0], acc[nt][1], acc[nt][2], acc[nt][3],
                         a0, a1, a2, a3, (u32)w, (u32)(w >> 32));
            }
        }
        const float qs = 0.17677669529663687f;  // 32^-0.5
        #pragma unroll
        for (int nt = 0; nt < 9; nt++) {
            int col0 = 72*ng + 8*nt + 2*tig;
            float sc = (72*ng + 8*nt < 96) ? qs : 1.0f;
            *(float2*)&qkv[(16*mt + gid)*QKV_LD + col0] =
                make_float2(tf32r(acc[nt][0]*sc), tf32r(acc[nt][1]*sc));
            *(float2*)&qkv[(16*mt + gid + 8)*QKV_LD + col0] =
                make_float2(tf32r(acc[nt][2]*sc), tf32r(acc[nt][3]*sc));
        }
    }
    __syncthreads();

    // ---- S = qK^T + bias (MMA): per head, ng covers 16 cols (2 n-tiles) ----
    #pragma unroll
    for (int h = 0; h < 3; h++) {
        float acc[2][4];
        #pragma unroll
        for (int j = 0; j < 2; j++)
            acc[j][0] = acc[j][1] = acc[j][2] = acc[j][3] = 0.f;
        #pragma unroll
        for (int ks = 0; ks < 4; ks++) {
            const float* ap = &qkv[(16*mt + gid)*QKV_LD + h*32 + 8*ks];
            u32 a0 = __float_as_uint(ap[tig]);
            u32 a1 = __float_as_uint(ap[8*QKV_LD + tig]);
            u32 a2 = __float_as_uint(ap[tig+4]);
            u32 a3 = __float_as_uint(ap[8*QKV_LD + tig+4]);
            #pragma unroll
            for (int j = 0; j < 2; j++) {
                const float* bp = &qkv[(ng*16 + j*8 + gid)*QKV_LD + 96 + h*32 + 8*ks];
                u32 b0 = __float_as_uint(bp[tig]);
                u32 b1 = __float_as_uint(bp[tig+4]);
                mma_tf32(acc[j][0], acc[j][1], acc[j][2], acc[j][3],
                         a0, a1, a2, a3, b0, b1);
            }
        }
        const float* bh = biasM + h*4096;
        #pragma unroll
        for (int j = 0; j < 2; j++) {
            int col = ng*16 + j*8 + 2*tig;
            int q0  = 16*mt + gid;
            float2 bb0 = *(const float2*)&bh[q0*64 + col];
            float2 bb1 = *(const float2*)&bh[(q0+8)*64 + col];
            *(float2*)&S3[(h*64 + q0)*S_LD + col] =
                make_float2(acc[j][0] + bb0.x, acc[j][1] + bb0.y);
            *(float2*)&S3[(h*64 + q0 + 8)*S_LD + col] =
                make_float2(acc[j][2] + bb1.x, acc[j][3] + bb1.y);
        }
    }
    __syncthreads();

    // ---- softmax: 8 lanes per row, all heads; probs tf32-rounded ----
    {
        int row = tid >> 3, sub = tid & 7;
        #pragma unroll
        for (int h = 0; h < 3; h++) {
            float* Sr = &S3[(h*64 + row)*S_LD + sub*8];
            float4 v0 = *(float4*)Sr;
            float4 v1 = *(float4*)(Sr + 4);
            float vals[8] = {v0.x,v0.y,v0.z,v0.w, v1.x,v1.y,v1.z,v1.w};
            float m = vals[0];
            #pragma unroll
            for (int c = 1; c < 8; c++) m = fmaxf(m, vals[c]);
            m = fmaxf(m, __shfl_xor_sync(0xffffffffu, m, 1));
            m = fmaxf(m, __shfl_xor_sync(0xffffffffu, m, 2));
            m = fmaxf(m, __shfl_xor_sync(0xffffffffu, m, 4));
            float ssum = 0.f;
            #pragma unroll
            for (int c = 0; c < 8; c++) { vals[c] = __expf(vals[c] - m); ssum += vals[c]; }
            ssum += __shfl_xor_sync(0xffffffffu, ssum, 1);
            ssum += __shfl_xor_sync(0xffffffffu, ssum, 2);
            ssum += __shfl_xor_sync(0xffffffffu, ssum, 4);
            float inv = 1.0f / ssum;
            *(float4*)Sr = make_float4(tf32r(vals[0]*inv), tf32r(vals[1]*inv),
                                       tf32r(vals[2]*inv), tf32r(vals[3]*inv));
            *(float4*)(Sr+4) = make_float4(tf32r(vals[4]*inv), tf32r(vals[5]*inv),
                                           tf32r(vals[6]*inv), tf32r(vals[7]*inv));
        }
    }
    __syncthreads();

    // ---- P@V (MMA): output 64x96, ng covers 24 cols (3 n-tiles) ----
    {
        float acc[3][4];
        #pragma unroll
        for (int j = 0; j < 3; j++)
            acc[j][0] = acc[j][1] = acc[j][2] = acc[j][3] = 0.f;
        #pragma unroll
        for (int j = 0; j < 3; j++) {
            int ct = ng*24 + j*8;
            int h  = ct >> 5;
            int dc = ct & 31;
            #pragma unroll
            for (int ks = 0; ks < 8; ks++) {
                const float* ap = &S3[(h*64 + 16*mt + gid)*S_LD + 8*ks];
                u32 a0 = __float_as_uint(ap[tig]);
                u32 a1 = __float_as_uint(ap[8*S_LD + tig]);
                u32 a2 = __float_as_uint(ap[tig+4]);
                u32 a3 = __float_as_uint(ap[8*S_LD + tig+4]);
                const float* bp = &qkv[(8*ks + tig)*QKV_LD + 192 + h*32 + dc + gid];
                u32 b0 = __float_as_uint(bp[0]);
                u32 b1 = __float_as_uint(bp[4*QKV_LD]);
                mma_tf32(acc[j][0], acc[j][1], acc[j][2], acc[j][3],
                         a0, a1, a2, a3, b0, b1);
            }
        }
        __syncthreads();   // xw/ao alias: ensure no one still needs xw (dead) / ordering
        #pragma unroll
        for (int j = 0; j < 3; j++) {
            int ct = ng*24 + j*8 + 2*tig;
            *(float2*)&ao[(16*mt + gid)*XW_LD + ct] =
                make_float2(tf32r(acc[j][0]), tf32r(acc[j][1]));
            *(float2*)&ao[(16*mt + gid + 8)*XW_LD + ct] =
                make_float2(tf32r(acc[j][2]), tf32r(acc[j][3]));
        }
    }
    __syncthreads();

    // ---- proj (MMA) + bias + residual -> global (shifted) ----
    {
        float acc[3][4];
        #pragma unroll
        for (int j = 0; j < 3; j++)
            acc[j][0] = acc[j][1] = acc[j][2] = acc[j][3] = 0.f;
        #pragma unroll
        for (int kt = 0; kt < 12; kt++) {
            const float* ap = &ao[(16*mt + gid)*XW_LD + 8*kt];
            u32 a0 = __float_as_uint(ap[tig]);
            u32 a1 = __float_as_uint(ap[8*XW_LD + tig]);
            u32 a2 = __float_as_uint(ap[tig+4]);
            u32 a3 = __float_as_uint(ap[8*XW_LD + tig+4]);
            #pragma unroll
            for (int j = 0; j < 3; j++) {
                u64 w = Wpf[(kt*12 + ng*3 + j)*32 + lane];
                mma_tf32(acc[j][0], acc[j][1], acc[j][2], acc[j][3],
                         a0, a1, a2, a3, (u32)w, (u32)(w >> 32));
            }
        }
        // epilogue: two rows per fragment
        int q0 = 16*mt + gid;
        #pragma unroll
        for (int rr = 0; rr < 2; rr++) {
            int t = q0 + 8*rr;
            int td = t >> 4, th = (t >> 2) & 3, tw = t & 3;
            int gd = (wd*4 + td + shift) & 63;
            int gh = (wh*4 + th + shift) & 63;
            int gw = (ww*4 + tw + shift) & 63;
            size_t idx = (size_t)((((b*64 + gd)*64 + gh)*64 + gw)) * 96;
            const float* rx = x + idx;
            float* dst = out + idx;
            #pragma unroll
            for (int j = 0; j < 3; j++) {
                int ct = ng*24 + j*8 + 2*tig;
                float2 bb = *(const float2*)&Bp[ct];
                float2 rv = *(const float2*)&rx[ct];
                *(float2*)&dst[ct] = make_float2(
                    acc[j][2*rr]   + bb.x + rv.x,
                    acc[j][2*rr+1] + bb.y + rv.y);
            }
        }
    }
}

// ---------------------------------------------------------------------------
// MLP block (unchanged from R7): LN2 -> GEMM1(MMA) -> GELU -> GEMM2(MMA)
// ---------------------------------------------------------------------------
__global__ __launch_bounds__(512, 1) void mlp_kernel(
    float* __restrict__ xa,
    const float* __restrict__ g2, const float* __restrict__ b2ln,
    const u64*  __restrict__ W1f, const float* __restrict__ B1,
    const u64*  __restrict__ W2f, const float* __restrict__ B2)
{
    extern __shared__ float sm[];
    float* y  = sm;             // 64 x XW_LD
    float* hb = y + 64*XW_LD;   // 64 x HB_LD

    const int tid  = threadIdx.x;
    const int lane = tid & 31;
    const int warp = tid >> 5;
    const size_t base = (size_t)blockIdx.x * 64;

    const int mt = warp & 3, ng = warp >> 2;
    const int gid = lane >> 2, tig = lane & 3;

    for (int t = warp; t < 64; t += 16) {
        const float* src = xa + (base + t) * 96;
        float v0 = src[lane], v1 = src[lane+32], v2 = src[lane+64];
        float s  = v0 + v1 + v2;
        float sq = v0*v0 + v1*v1 + v2*v2;
        #pragma unroll
        for (int o = 16; o; o >>= 1) {
            s  += __shfl_xor_sync(0xffffffffu, s,  o);
            sq += __shfl_xor_sync(0xffffffffu, sq, o);
        }
        float mean = s * (1.0f/96.0f);
        float var  = sq * (1.0f/96.0f) - mean*mean;
        float rstd = rsqrtf(var + 1e-5f);
        y[t*XW_LD+lane]    = tf32r((v0-mean)*rstd*g2[lane]    + b2ln[lane]);
        y[t*XW_LD+lane+32] = tf32r((v1-mean)*rstd*g2[lane+32] + b2ln[lane+32]);
        y[t*XW_LD+lane+64] = tf32r((v2-mean)*rstd*g2[lane+64] + b2ln[lane+64]);
    }
    __syncthreads();

    {
        float acc[12][4];
        #pragma unroll
        for (int nt = 0; nt < 12; nt++)
            acc[nt][0] = acc[nt][1] = acc[nt][2] = acc[nt][3] = 0.f;
        #pragma unroll
        for (int kt = 0; kt < 12; kt++) {
            const float* arow0 = &y[(16*mt + gid)*XW_LD + 8*kt];
            const float* arow1 = arow0 + 8*XW_LD;
            u32 a0 = __float_as_uint(arow0[tig]);
            u32 a1 = __float_as_uint(arow1[tig]);
            u32 a2 = __float_as_uint(arow0[tig+4]);
            u32 a3 = __float_as_uint(arow1[tig+4]);
            #pragma unroll
            for (int nt = 0; nt < 12; nt++) {
                u64 w = W1f[(kt*48 + ng*12 + nt)*32 + lane];
                mma_tf32(acc[nt][0], acc[nt][1], acc[nt][2], acc[nt][3],
                         a0, a1, a2, a3, (u32)w, (u32)(w >> 32));
            }
        }
        #pragma unroll
        for (int nt = 0; nt < 12; nt++) {
            int col0 = 96*ng + 8*nt + 2*tig;
            float2 bb = *(const float2*)&B1[col0];
            float u0 = acc[nt][0] + bb.x, u1 = acc[nt][1] + bb.y;
            float u2 = acc[nt][2] + bb.x, u3 = acc[nt][3] + bb.y;
            float g0 = 0.5f*u0*(1.0f + erff(u0*0.70710678118654752f));
            float g1v= 0.5f*u1*(1.0f + erff(u1*0.70710678118654752f));
            float g2v= 0.5f*u2*(1.0f + erff(u2*0.70710678118654752f));
            float g3 = 0.5f*u3*(1.0f + erff(u3*0.70710678118654752f));
            *(float2*)&hb[(16*mt + gid)*HB_LD + col0]     = make_float2(tf32r(g0), tf32r(g1v));
            *(float2*)&hb[(16*mt + gid + 8)*HB_LD + col0] = make_float2(tf32r(g2v), tf32r(g3));
        }
    }
    __syncthreads();

    {
        float acc[3][4];
        #pragma unroll
        for (int nt = 0; nt < 3; nt++)
            acc[nt][0] = acc[nt][1] = acc[nt][2] = acc[nt][3] = 0.f;
        #pragma unroll
        for (int kt = 0; kt < 48; kt++) {
            const float* arow0 = &hb[(16*mt + gid)*HB_LD + 8*kt];
            const float* arow1 = arow0 + 8*HB_LD;
            u32 a0 = __float_as_uint(arow0[tig]);
            u32 a1 = __float_as_uint(arow1[tig]);
            u32 a2 = __float_as_uint(arow0[tig+4]);
            u32 a3 = __float_as_uint(arow1[tig+4]);
            #pragma unroll
            for (int nt = 0; nt < 3; nt++) {
                u64 w = W2f[(kt*12 + ng*3 + nt)*32 + lane];
                mma_tf32(acc[nt][0], acc[nt][1], acc[nt][2], acc[nt][3],
                         a0, a1, a2, a3, (u32)w, (u32)(w >> 32));
            }
        }
        #pragma unroll
        for (int nt = 0; nt < 3; nt++) {
            int col0 = 24*ng + 8*nt + 2*tig;
            float2 bb = *(const float2*)&B2[col0];
            float* p0 = xa + (base + 16*mt + gid) * 96 + col0;
            float* p1 = xa + (base + 16*mt + gid + 8) * 96 + col0;
            float2 r0 = *(float2*)p0;
            float2 r1 = *(float2*)p1;
            *(float2*)p0 = make_float2(acc[nt][0] + bb.x + r0.x, acc[nt][1] + bb.y + r0.y);
            *(float2*)p1 = make_float2(acc[nt][2] + bb.x + r1.x, acc[nt][3] + bb.y + r1.y);
        }
    }
}

// ---------------------------------------------------------------------------
extern "C" void kernel_launch(void* const* d_in, const int* in_sizes, int n_in,
                              void* d_out, int out_size)
{
    const float* x      = (const float*)d_in[0];
    const float* qkv_w  = (const float*)d_in[1];
    const float* qkv_b  = (const float*)d_in[2];
    const float* proj_w = (const float*)d_in[3];
    const float* proj_b = (const float*)d_in[4];
    const float* btab   = (const float*)d_in[5];
    const float* ln1g   = (const float*)d_in[6];
    const float* ln1b   = (const float*)d_in[7];
    const float* ln2g   = (const float*)d_in[8];
    const float* ln2b   = (const float*)d_in[9];
    const float* w1     = (const float*)d_in[10];
    const float* b1     = (const float*)d_in[11];
    const float* w2     = (const float*)d_in[12];
    const float* b2     = (const float*)d_in[13];
    float* out = (float*)d_out;

    float* scratch = nullptr;
    u64 *wqkvf = nullptr, *w1f = nullptr, *w2f = nullptr, *wpf = nullptr;
    float* biasm = nullptr;
    cudaGetSymbolAddress((void**)&scratch, g_scratch);
    cudaGetSymbolAddress((void**)&wqkvf,   g_wqkvf);
    cudaGetSymbolAddress((void**)&w1f,     g_w1f);
    cudaGetSymbolAddress((void**)&w2f,     g_w2f);
    cudaGetSymbolAddress((void**)&wpf,     g_wpf);
    cudaGetSymbolAddress((void**)&biasm,   g_bias);

    cudaFuncSetAttribute(attn_kernel, cudaFuncAttributeMaxDynamicSharedMemorySize, ASMEM);
    cudaFuncSetAttribute(mlp_kernel,  cudaFuncAttributeMaxDynamicSharedMemorySize, MSMEM);

    // Prep: fragment-pack weights + dense bias matrices
    {
        int tq = 2*12*36*32, t1 = 2*12*48*32, t2 = 2*48*12*32, tp = 2*12*12*32;
        pack_kernel<<<(tq+255)/256, 256>>>(qkv_w, wqkvf, 12, 36, 288, tq);
        pack_kernel<<<(t1+255)/256, 256>>>(w1,    w1f,   12, 48, 384, t1);
        pack_kernel<<<(t2+255)/256, 256>>>(w2,    w2f,   48, 12,  96, t2);
        pack_kernel<<<(tp+255)/256, 256>>>(proj_w, wpf,  12, 12,  96, tp);
        bias_kernel<<<(2*3*64*64+255)/256, 256>>>(btab);
    }

    // ---- block 0 (shift 0) ----
    attn_kernel<<<NWIN, 512, ASMEM>>>(x, scratch,
        wqkvf, qkv_b, wpf, proj_b, biasm, ln1g, ln1b, 0);
    mlp_kernel<<<TOKENS/64, 512, MSMEM>>>(scratch,
        ln2g, ln2b, w1f, b1, w2f, b2);

    // ---- block 1 (shift 2) ----
    attn_kernel<<<NWIN, 512, ASMEM>>>(scratch, out,
        wqkvf + 12*36*32, qkv_b + 288, wpf + 12*12*32, proj_b + 96,
        biasm + 3*64*64, ln1g + 96, ln1b + 96, 2);
    mlp_kernel<<<TOKENS/64, 512, MSMEM>>>(out,
        ln2g + 96, ln2b + 96, w1f + 12*48*32, b1 + 384, w2f + 48*12*32, b2 + 96);
}

// round 10
// speedup vs baseline: 1.0061x; 1.0061x over previous
#include <cuda_runtime.h>
#include <math.h>

typedef unsigned long long u64;
typedef unsigned int u32;

#define CDIM   96
#define NWIN   8192
#define TOKENS (2*64*64*64)
#define QKV_LD 292          // %32==4, 16B-aligned rows
#define S_LD   68
#define XW_LD  100          // %32==4 -> conflict-free mma A-fragment LDS
#define HB_LD  388          // %32==4

// Static device scratch (no allocs allowed)
__device__ float g_scratch[(size_t)TOKENS * CDIM];
// Fragment-packed tf32 weights (u64 = {b0 lo, b1 hi})
__device__ u64 g_wqkvf[2 * 12 * 36 * 32];   // K=96 (KT12), N=288 (NT36)
__device__ u64 g_w1f  [2 * 12 * 48 * 32];   // K=96,  N=384
__device__ u64 g_w2f  [2 * 48 * 12 * 32];   // K=384, N=96
__device__ u64 g_wpf  [2 * 12 * 12 * 32];   // K=96,  N=96 (proj)
// Dense rel-pos bias: [layer][head][q=64][k=64]
__device__ float g_bias[2 * 3 * 64 * 64];

#define ASMEM ((64*XW_LD + 64*QKV_LD + 3*64*S_LD) * 4)
#define MSMEM ((64*XW_LD + 64*HB_LD) * 4)

// ---- tf32 helpers ----
__device__ __forceinline__ u32 tf32bits(float x) {
    u32 r; asm("cvt.rna.tf32.f32 %0,%1;" : "=r"(r) : "f"(x)); return r;
}
__device__ __forceinline__ float tf32r(float x) {
    return __uint_as_float(tf32bits(x));
}
__device__ __forceinline__ void mma_tf32(
    float& c0, float& c1, float& c2, float& c3,
    u32 a0, u32 a1, u32 a2, u32 a3, u32 b0, u32 b1)
{
    asm("mma.sync.aligned.m16n8k8.row.col.f32.tf32.tf32.f32 "
        "{%0,%1,%2,%3},{%4,%5,%6,%7},{%8,%9},{%0,%1,%2,%3};"
        : "+f"(c0), "+f"(c1), "+f"(c2), "+f"(c3)
        : "r"(a0), "r"(a1), "r"(a2), "r"(a3), "r"(b0), "r"(b1));
}

// ---------------------------------------------------------------------------
// Pack row-major W[K][N] (per layer) into mma B-fragment order.
// ---------------------------------------------------------------------------
__global__ void pack_kernel(const float* __restrict__ W, u64* __restrict__ dst,
                            int KT, int NT, int N, int total)
{
    int i = blockIdx.x * blockDim.x + threadIdx.x;
    if (i >= total) return;
    int per_layer = KT * NT * 32;
    int layer = i / per_layer;
    int r = i - layer * per_layer;
    int t = r >> 5, lane = r & 31;
    int kt = t / NT, nt = t - kt * NT;
    int k = kt * 8 + (lane & 3);
    int n = nt * 8 + (lane >> 2);
    const float* Wl = W + (size_t)layer * (KT * 8) * N;
    u32 lo = tf32bits(Wl[(size_t)k * N + n]);
    u32 hi = tf32bits(Wl[(size_t)(k + 4) * N + n]);
    dst[i] = ((u64)hi << 32) | lo;
}

// ---------------------------------------------------------------------------
// Precompute dense rel-pos bias matrices (window-invariant).
// ---------------------------------------------------------------------------
__global__ void bias_kernel(const float* __restrict__ tb) {
    int i = blockIdx.x * blockDim.x + threadIdx.x;
    if (i >= 2*3*64*64) return;
    int layer = i / (3*4096);
    int r = i % (3*4096);
    int h = r / 4096;
    int qk = r & 4095;
    int q = qk >> 6, k = qk & 63;
    int qd = q >> 4, qh = (q >> 2) & 3, qw = q & 3;
    int kd = k >> 4, kh = (k >> 2) & 3, kw = k & 3;
    int ridx = (qd-kd+3)*49 + (qh-kh+3)*7 + (qw-kw+3);
    g_bias[i] = tb[layer*1029 + ridx*3 + h];
}

// ---------------------------------------------------------------------------
// Attention block, all GEMMs on tensor cores.
// One CTA per 4x4x4 window, 512 threads (16 warps: mt=warp&3, ng=warp>>2).
// ---------------------------------------------------------------------------
__global__ __launch_bounds__(512, 1) void attn_kernel(
    const float* __restrict__ x, float* __restrict__ out,
    const u64*  __restrict__ Wqkvf, const float* __restrict__ Bqkv,
    const u64*  __restrict__ Wpf,   const float* __restrict__ Bp,
    const float* __restrict__ biasM,
    const float* __restrict__ g1,   const float* __restrict__ b1,
    int shift)
{
    extern __shared__ float sm[];
    float* xw  = sm;                    // 64 x XW_LD; later aliased as ao
    float* qkv = xw + 64*XW_LD;         // 64 x 292 (tf32-rounded)
    float* S3  = qkv + 64*QKV_LD;       // 3 x 64 x 68
    float* ao  = xw;

    const int tid  = threadIdx.x;
    const int lane = tid & 31;
    const int warp = tid >> 5;
    const int mt   = warp & 3;
    const int ng   = warp >> 2;
    const int gid  = lane >> 2;
    const int tig  = lane & 3;

    const int bw   = blockIdx.x;
    const int b    = bw >> 12;
    const int widx = bw & 4095;
    const int wd   = widx >> 8;
    const int wh   = (widx >> 4) & 15;
    const int ww   = widx & 15;

    // ---- LN1 (one warp per token), store tf32-rounded ----
    for (int t = warp; t < 64; t += 16) {
        int td = t >> 4, th = (t >> 2) & 3, tw = t & 3;
        int gd = (wd*4 + td + shift) & 63;
        int gh = (wh*4 + th + shift) & 63;
        int gw = (ww*4 + tw + shift) & 63;
        const float* src = x + (size_t)((((b*64 + gd)*64 + gh)*64 + gw)) * 96;
        float v0 = src[lane], v1 = src[lane+32], v2 = src[lane+64];
        float s  = v0 + v1 + v2;
        float sq = v0*v0 + v1*v1 + v2*v2;
        #pragma unroll
        for (int o = 16; o; o >>= 1) {
            s  += __shfl_xor_sync(0xffffffffu, s,  o);
            sq += __shfl_xor_sync(0xffffffffu, sq, o);
        }
        float mean = s * (1.0f/96.0f);
        float var  = sq * (1.0f/96.0f) - mean*mean;
        float rstd = rsqrtf(var + 1e-5f);
        xw[t*XW_LD+lane]    = tf32r((v0-mean)*rstd*g1[lane]    + b1[lane]);
        xw[t*XW_LD+lane+32] = tf32r((v1-mean)*rstd*g1[lane+32] + b1[lane+32]);
        xw[t*XW_LD+lane+64] = tf32r((v2-mean)*rstd*g1[lane+64] + b1[lane+64]);
    }
    __syncthreads();

    // ---- QKV GEMM (MMA): 9 n-tiles per warp; outputs tf32-rounded, q scaled ----
    {
        float acc[9][4];
        #pragma unroll
        for (int nt = 0; nt < 9; nt++) {
            int col0 = 72*ng + 8*nt + 2*tig;
            float2 bb = *(const float2*)&Bqkv[col0];
            acc[nt][0] = bb.x; acc[nt][1] = bb.y;
            acc[nt][2] = bb.x; acc[nt][3] = bb.y;
        }
        #pragma unroll
        for (int kt = 0; kt < 12; kt++) {
            const float* arow0 = &xw[(16*mt + gid)*XW_LD + 8*kt];
            const float* arow1 = arow0 + 8*XW_LD;
            u32 a0 = __float_as_uint(arow0[tig]);
            u32 a1 = __float_as_uint(arow1[tig]);
            u32 a2 = __float_as_uint(arow0[tig+4]);
            u32 a3 = __float_as_uint(arow1[tig+4]);
            #pragma unroll
            for (int nt = 0; nt < 9; nt++) {
                u64 w = Wqkvf[(kt*36 + ng*9 + nt)*32 + lane];
                mma_tf32(acc[nt][0], acc[nt][1], acc[nt][2], acc[nt][3],
                         a0, a1, a2, a3, (u32)w, (u32)(w >> 32));
            }
        }
        const float qs = 0.17677669529663687f;  // 32^-0.5
        #pragma unroll
        for (int nt = 0; nt < 9; nt++) {
            int col0 = 72*ng + 8*nt + 2*tig;
            float sc = (72*ng + 8*nt < 96) ? qs : 1.0f;
            *(float2*)&qkv[(16*mt + gid)*QKV_LD + col0] =
                make_float2(tf32r(acc[nt][0]*sc), tf32r(acc[nt][1]*sc));
            *(float2*)&qkv[(16*mt + gid + 8)*QKV_LD + col0] =
                make_float2(tf32r(acc[nt][2]*sc), tf32r(acc[nt][3]*sc));
        }
    }
    __syncthreads();

    // ---- S = qK^T + bias (MMA): per head, ng covers 16 cols (2 n-tiles) ----
    #pragma unroll
    for (int h = 0; h < 3; h++) {
        float acc[2][4];
        #pragma unroll
        for (int j = 0; j < 2; j++)
            acc[j][0] = acc[j][1] = acc[j][2] = acc[j][3] = 0.f;
        #pragma unroll
        for (int ks = 0; ks < 4; ks++) {
            const float* ap = &qkv[(16*mt + gid)*QKV_LD + h*32 + 8*ks];
            u32 a0 = __float_as_uint(ap[tig]);
            u32 a1 = __float_as_uint(ap[8*QKV_LD + tig]);
            u32 a2 = __float_as_uint(ap[tig+4]);
            u32 a3 = __float_as_uint(ap[8*QKV_LD + tig+4]);
            #pragma unroll
            for (int j = 0; j < 2; j++) {
                const float* bp = &qkv[(ng*16 + j*8 + gid)*QKV_LD + 96 + h*32 + 8*ks];
                u32 b0 = __float_as_uint(bp[tig]);
                u32 b1 = __float_as_uint(bp[tig+4]);
                mma_tf32(acc[j][0], acc[j][1], acc[j][2], acc[j][3],
                         a0, a1, a2, a3, b0, b1);
            }
        }
        const float* bh = biasM + h*4096;
        #pragma unroll
        for (int j = 0; j < 2; j++) {
            int col = ng*16 + j*8 + 2*tig;
            int q0  = 16*mt + gid;
            float2 bb0 = *(const float2*)&bh[q0*64 + col];
            float2 bb1 = *(const float2*)&bh[(q0+8)*64 + col];
            *(float2*)&S3[(h*64 + q0)*S_LD + col] =
                make_float2(acc[j][0] + bb0.x, acc[j][1] + bb0.y);
            *(float2*)&S3[(h*64 + q0 + 8)*S_LD + col] =
                make_float2(acc[j][2] + bb1.x, acc[j][3] + bb1.y);
        }
    }
    __syncthreads();

    // ---- softmax: 8 lanes per row, all heads; probs tf32-rounded ----
    {
        int row = tid >> 3, sub = tid & 7;
        #pragma unroll
        for (int h = 0; h < 3; h++) {
            float* Sr = &S3[(h*64 + row)*S_LD + sub*8];
            float4 v0 = *(float4*)Sr;
            float4 v1 = *(float4*)(Sr + 4);
            float vals[8] = {v0.x,v0.y,v0.z,v0.w, v1.x,v1.y,v1.z,v1.w};
            float m = vals[0];
            #pragma unroll
            for (int c = 1; c < 8; c++) m = fmaxf(m, vals[c]);
            m = fmaxf(m, __shfl_xor_sync(0xffffffffu, m, 1));
            m = fmaxf(m, __shfl_xor_sync(0xffffffffu, m, 2));
            m = fmaxf(m, __shfl_xor_sync(0xffffffffu, m, 4));
            float ssum = 0.f;
            #pragma unroll
            for (int c = 0; c < 8; c++) { vals[c] = __expf(vals[c] - m); ssum += vals[c]; }
            ssum += __shfl_xor_sync(0xffffffffu, ssum, 1);
            ssum += __shfl_xor_sync(0xffffffffu, ssum, 2);
            ssum += __shfl_xor_sync(0xffffffffu, ssum, 4);
            float inv = 1.0f / ssum;
            *(float4*)Sr = make_float4(tf32r(vals[0]*inv), tf32r(vals[1]*inv),
                                       tf32r(vals[2]*inv), tf32r(vals[3]*inv));
            *(float4*)(Sr+4) = make_float4(tf32r(vals[4]*inv), tf32r(vals[5]*inv),
                                           tf32r(vals[6]*inv), tf32r(vals[7]*inv));
        }
    }
    __syncthreads();

    // ---- P@V (MMA): output 64x96, ng covers 24 cols (3 n-tiles) ----
    {
        float acc[3][4];
        #pragma unroll
        for (int j = 0; j < 3; j++)
            acc[j][0] = acc[j][1] = acc[j][2] = acc[j][3] = 0.f;
        #pragma unroll
        for (int j = 0; j < 3; j++) {
            int ct = ng*24 + j*8;
            int h  = ct >> 5;
            int dc = ct & 31;
            #pragma unroll
            for (int ks = 0; ks < 8; ks++) {
                const float* ap = &S3[(h*64 + 16*mt + gid)*S_LD + 8*ks];
                u32 a0 = __float_as_uint(ap[tig]);
                u32 a1 = __float_as_uint(ap[8*S_LD + tig]);
                u32 a2 = __float_as_uint(ap[tig+4]);
                u32 a3 = __float_as_uint(ap[8*S_LD + tig+4]);
                const float* bp = &qkv[(8*ks + tig)*QKV_LD + 192 + h*32 + dc + gid];
                u32 b0 = __float_as_uint(bp[0]);
                u32 b1 = __float_as_uint(bp[4*QKV_LD]);
                mma_tf32(acc[j][0], acc[j][1], acc[j][2], acc[j][3],
                         a0, a1, a2, a3, b0, b1);
            }
        }
        __syncthreads();   // xw/ao alias: ensure no one still needs xw (dead) / ordering
        #pragma unroll
        for (int j = 0; j < 3; j++) {
            int ct = ng*24 + j*8 + 2*tig;
            *(float2*)&ao[(16*mt + gid)*XW_LD + ct] =
                make_float2(tf32r(acc[j][0]), tf32r(acc[j][1]));
            *(float2*)&ao[(16*mt + gid + 8)*XW_LD + ct] =
                make_float2(tf32r(acc[j][2]), tf32r(acc[j][3]));
        }
    }
    __syncthreads();

    // ---- proj (MMA) + bias + residual -> global (shifted) ----
    {
        float acc[3][4];
        #pragma unroll
        for (int j = 0; j < 3; j++)
            acc[j][0] = acc[j][1] = acc[j][2] = acc[j][3] = 0.f;
        #pragma unroll
        for (int kt = 0; kt < 12; kt++) {
            const float* ap = &ao[(16*mt + gid)*XW_LD + 8*kt];
            u32 a0 = __float_as_uint(ap[tig]);
            u32 a1 = __float_as_uint(ap[8*XW_LD + tig]);
            u32 a2 = __float_as_uint(ap[tig+4]);
            u32 a3 = __float_as_uint(ap[8*XW_LD + tig+4]);
            #pragma unroll
            for (int j = 0; j < 3; j++) {
                u64 w = Wpf[(kt*12 + ng*3 + j)*32 + lane];
                mma_tf32(acc[j][0], acc[j][1], acc[j][2], acc[j][3],
                         a0, a1, a2, a3, (u32)w, (u32)(w >> 32));
            }
        }
        // epilogue: two rows per fragment
        int q0 = 16*mt + gid;
        #pragma unroll
        for (int rr = 0; rr < 2; rr++) {
            int t = q0 + 8*rr;
            int td = t >> 4, th = (t >> 2) & 3, tw = t & 3;
            int gd = (wd*4 + td + shift) & 63;
            int gh = (wh*4 + th + shift) & 63;
            int gw = (ww*4 + tw + shift) & 63;
            size_t idx = (size_t)((((b*64 + gd)*64 + gh)*64 + gw)) * 96;
            const float* rx = x + idx;
            float* dst = out + idx;
            #pragma unroll
            for (int j = 0; j < 3; j++) {
                int ct = ng*24 + j*8 + 2*tig;
                float2 bb = *(const float2*)&Bp[ct];
                float2 rv = *(const float2*)&rx[ct];
                *(float2*)&dst[ct] = make_float2(
                    acc[j][2*rr]   + bb.x + rv.x,
                    acc[j][2*rr+1] + bb.y + rv.y);
            }
        }
    }
}

// ---------------------------------------------------------------------------
// MLP block (unchanged from R7): LN2 -> GEMM1(MMA) -> GELU -> GEMM2(MMA)
// ---------------------------------------------------------------------------
__global__ __launch_bounds__(512, 1) void mlp_kernel(
    float* __restrict__ xa,
    const float* __restrict__ g2, const float* __restrict__ b2ln,
    const u64*  __restrict__ W1f, const float* __restrict__ B1,
    const u64*  __restrict__ W2f, const float* __restrict__ B2)
{
    extern __shared__ float sm[];
    float* y  = sm;             // 64 x XW_LD
    float* hb = y + 64*XW_LD;   // 64 x HB_LD

    const int tid  = threadIdx.x;
    const int lane = tid & 31;
    const int warp = tid >> 5;
    const size_t base = (size_t)blockIdx.x * 64;

    const int mt = warp & 3, ng = warp >> 2;
    const int gid = lane >> 2, tig = lane & 3;

    for (int t = warp; t < 64; t += 16) {
        const float* src = xa + (base + t) * 96;
        float v0 = src[lane], v1 = src[lane+32], v2 = src[lane+64];
        float s  = v0 + v1 + v2;
        float sq = v0*v0 + v1*v1 + v2*v2;
        #pragma unroll
        for (int o = 16; o; o >>= 1) {
            s  += __shfl_xor_sync(0xffffffffu, s,  o);
            sq += __shfl_xor_sync(0xffffffffu, sq, o);
        }
        float mean = s * (1.0f/96.0f);
        float var  = sq * (1.0f/96.0f) - mean*mean;
        float rstd = rsqrtf(var + 1e-5f);
        y[t*XW_LD+lane]    = tf32r((v0-mean)*rstd*g2[lane]    + b2ln[lane]);
        y[t*XW_LD+lane+32] = tf32r((v1-mean)*rstd*g2[lane+32] + b2ln[lane+32]);
        y[t*XW_LD+lane+64] = tf32r((v2-mean)*rstd*g2[lane+64] + b2ln[lane+64]);
    }
    __syncthreads();

    {
        float acc[12][4];
        #pragma unroll
        for (int nt = 0; nt < 12; nt++)
            acc[nt][0] = acc[nt][1] = acc[nt][2] = acc[nt][3] = 0.f;
        #pragma unroll
        for (int kt = 0; kt < 12; kt++) {
            const float* arow0 = &y[(16*mt + gid)*XW_LD + 8*kt];
            const float* arow1 = arow0 + 8*XW_LD;
            u32 a0 = __float_as_uint(arow0[tig]);
            u32 a1 = __float_as_uint(arow1[tig]);
            u32 a2 = __float_as_uint(arow0[tig+4]);
            u32 a3 = __float_as_uint(arow1[tig+4]);
            #pragma unroll
            for (int nt = 0; nt < 12; nt++) {
                u64 w = W1f[(kt*48 + ng*12 + nt)*32 + lane];
                mma_tf32(acc[nt][0], acc[nt][1], acc[nt][2], acc[nt][3],
                         a0, a1, a2, a3, (u32)w, (u32)(w >> 32));
            }
        }
        #pragma unroll
        for (int nt = 0; nt < 12; nt++) {
            int col0 = 96*ng + 8*nt + 2*tig;
            float2 bb = *(const float2*)&B1[col0];
            float u0 = acc[nt][0] + bb.x, u1 = acc[nt][1] + bb.y;
            float u2 = acc[nt][2] + bb.x, u3 = acc[nt][3] + bb.y;
            float g0 = 0.5f*u0*(1.0f + erff(u0*0.70710678118654752f));
            float g1v= 0.5f*u1*(1.0f + erff(u1*0.70710678118654752f));
            float g2v= 0.5f*u2*(1.0f + erff(u2*0.70710678118654752f));
            float g3 = 0.5f*u3*(1.0f + erff(u3*0.70710678118654752f));
            *(float2*)&hb[(16*mt + gid)*HB_LD + col0]     = make_float2(tf32r(g0), tf32r(g1v));
            *(float2*)&hb[(16*mt + gid + 8)*HB_LD + col0] = make_float2(tf32r(g2v), tf32r(g3));
        }
    }
    __syncthreads();

    {
        float acc[3][4];
        #pragma unroll
        for (int nt = 0; nt < 3; nt++)
            acc[nt][0] = acc[nt][1] = acc[nt][2] = acc[nt][3] = 0.f;
        #pragma unroll
        for (int kt = 0; kt < 48; kt++) {
            const float* arow0 = &hb[(16*mt + gid)*HB_LD + 8*kt];
            const float* arow1 = arow0 + 8*HB_LD;
            u32 a0 = __float_as_uint(arow0[tig]);
            u32 a1 = __float_as_uint(arow1[tig]);
            u32 a2 = __float_as_uint(arow0[tig+4]);
            u32 a3 = __float_as_uint(arow1[tig+4]);
            #pragma unroll
            for (int nt = 0; nt < 3; nt++) {
                u64 w = W2f[(kt*12 + ng*3 + nt)*32 + lane];
                mma_tf32(acc[nt][0], acc[nt][1], acc[nt][2], acc[nt][3],
                         a0, a1, a2, a3, (u32)w, (u32)(w >> 32));
            }
        }
        #pragma unroll
        for (int nt = 0; nt < 3; nt++) {
            int col0 = 24*ng + 8*nt + 2*tig;
            float2 bb = *(const float2*)&B2[col0];
            float* p0 = xa + (base + 16*mt + gid) * 96 + col0;
            float* p1 = xa + (base + 16*mt + gid + 8) * 96 + col0;
            float2 r0 = *(float2*)p0;
            float2 r1 = *(float2*)p1;
            *(float2*)p0 = make_float2(acc[nt][0] + bb.x + r0.x, acc[nt][1] + bb.y + r0.y);
            *(float2*)p1 = make_float2(acc[nt][2] + bb.x + r1.x, acc[nt][3] + bb.y + r1.y);
        }
    }
}

// ---------------------------------------------------------------------------
extern "C" void kernel_launch(void* const* d_in, const int* in_sizes, int n_in,
                              void* d_out, int out_size)
{
    const float* x      = (const float*)d_in[0];
    const float* qkv_w  = (const float*)d_in[1];
    const float* qkv_b  = (const float*)d_in[2];
    const float* proj_w = (const float*)d_in[3];
    const float* proj_b = (const float*)d_in[4];
    const float* btab   = (const float*)d_in[5];
    const float* ln1g   = (const float*)d_in[6];
    const float* ln1b   = (const float*)d_in[7];
    const float* ln2g   = (const float*)d_in[8];
    const float* ln2b   = (const float*)d_in[9];
    const float* w1     = (const float*)d_in[10];
    const float* b1     = (const float*)d_in[11];
    const float* w2     = (const float*)d_in[12];
    const float* b2     = (const float*)d_in[13];
    float* out = (float*)d_out;

    float* scratch = nullptr;
    u64 *wqkvf = nullptr, *w1f = nullptr, *w2f = nullptr, *wpf = nullptr;
    float* biasm = nullptr;
    cudaGetSymbolAddress((void**)&scratch, g_scratch);
    cudaGetSymbolAddress((void**)&wqkvf,   g_wqkvf);
    cudaGetSymbolAddress((void**)&w1f,     g_w1f);
    cudaGetSymbolAddress((void**)&w2f,     g_w2f);
    cudaGetSymbolAddress((void**)&wpf,     g_wpf);
    cudaGetSymbolAddress((void**)&biasm,   g_bias);

    cudaFuncSetAttribute(attn_kernel, cudaFuncAttributeMaxDynamicSharedMemorySize, ASMEM);
    cudaFuncSetAttribute(mlp_kernel,  cudaFuncAttributeMaxDynamicSharedMemorySize, MSMEM);

    // Prep: fragment-pack weights + dense bias matrices
    {
        int tq = 2*12*36*32, t1 = 2*12*48*32, t2 = 2*48*12*32, tp = 2*12*12*32;
        pack_kernel<<<(tq+255)/256, 256>>>(qkv_w, wqkvf, 12, 36, 288, tq);
        pack_kernel<<<(t1+255)/256, 256>>>(w1,    w1f,   12, 48, 384, t1);
        pack_kernel<<<(t2+255)/256, 256>>>(w2,    w2f,   48, 12,  96, t2);
        pack_kernel<<<(tp+255)/256, 256>>>(proj_w, wpf,  12, 12,  96, tp);
        bias_kernel<<<(2*3*64*64+255)/256, 256>>>(btab);
    }

    // ---- block 0 (shift 0) ----
    attn_kernel<<<NWIN, 512, ASMEM>>>(x, scratch,
        wqkvf, qkv_b, wpf, proj_b, biasm, ln1g, ln1b, 0);
    mlp_kernel<<<TOKENS/64, 512, MSMEM>>>(scratch,
        ln2g, ln2b, w1f, b1, w2f, b2);

    // ---- block 1 (shift 2) ----
    attn_kernel<<<NWIN, 512, ASMEM>>>(scratch, out,
        wqkvf + 12*36*32, qkv_b + 288, wpf + 12*12*32, proj_b + 96,
        biasm + 3*64*64, ln1g + 96, ln1b + 96, 2);
    mlp_kernel<<<TOKENS/64, 512, MSMEM>>>(out,
        ln2g + 96, ln2b + 96, w1f + 12*48*32, b1 + 384, w2f + 48*12*32, b2 + 96);
}

// round 11
// speedup vs baseline: 1.0067x; 1.0006x over previous
#include <cuda_runtime.h>
#include <math.h>

typedef unsigned long long u64;
typedef unsigned int u32;

#define CDIM   96
#define NWIN   8192
#define TOKENS (2*64*64*64)
#define QKV_LD 292          // %32==4, 16B-aligned rows
#define S_LD   68
#define XW_LD  100          // %32==4 -> conflict-free mma A-fragment LDS
#define HB_LD  388          // %32==4

// Static device scratch (no allocs allowed)
__device__ float g_scratch[(size_t)TOKENS * CDIM];
// Fragment-packed tf32 weights (u64 = {b0 lo, b1 hi})
__device__ u64 g_wqkvf[2 * 12 * 36 * 32];   // K=96 (KT12), N=288 (NT36)
__device__ u64 g_w1f  [2 * 12 * 48 * 32];   // K=96,  N=384
__device__ u64 g_w2f  [2 * 48 * 12 * 32];   // K=384, N=96
__device__ u64 g_wpf  [2 * 12 * 12 * 32];   // K=96,  N=96 (proj)
// Dense rel-pos bias: [layer][head][q=64][k=64]
__device__ float g_bias[2 * 3 * 64 * 64];

#define ASMEM ((64*XW_LD + 64*QKV_LD + 3*64*S_LD) * 4)
#define MSMEM ((64*XW_LD + 64*HB_LD) * 4)

// ---- tf32 helpers ----
__device__ __forceinline__ u32 tf32bits(float x) {
    u32 r; asm("cvt.rna.tf32.f32 %0,%1;" : "=r"(r) : "f"(x)); return r;
}
__device__ __forceinline__ float tf32r(float x) {
    return __uint_as_float(tf32bits(x));
}
__device__ __forceinline__ void mma_tf32(
    float& c0, float& c1, float& c2, float& c3,
    u32 a0, u32 a1, u32 a2, u32 a3, u32 b0, u32 b1)
{
    asm("mma.sync.aligned.m16n8k8.row.col.f32.tf32.tf32.f32 "
        "{%0,%1,%2,%3},{%4,%5,%6,%7},{%8,%9},{%0,%1,%2,%3};"
        : "+f"(c0), "+f"(c1), "+f"(c2), "+f"(c3)
        : "r"(a0), "r"(a1), "r"(a2), "r"(a3), "r"(b0), "r"(b1));
}

// ---------------------------------------------------------------------------
// Pack row-major W[K][N] (per layer) into mma B-fragment order.
// ---------------------------------------------------------------------------
__global__ void pack_kernel(const float* __restrict__ W, u64* __restrict__ dst,
                            int KT, int NT, int N, int total)
{
    int i = blockIdx.x * blockDim.x + threadIdx.x;
    if (i >= total) return;
    int per_layer = KT * NT * 32;
    int layer = i / per_layer;
    int r = i - layer * per_layer;
    int t = r >> 5, lane = r & 31;
    int kt = t / NT, nt = t - kt * NT;
    int k = kt * 8 + (lane & 3);
    int n = nt * 8 + (lane >> 2);
    const float* Wl = W + (size_t)layer * (KT * 8) * N;
    u32 lo = tf32bits(Wl[(size_t)k * N + n]);
    u32 hi = tf32bits(Wl[(size_t)(k + 4) * N + n]);
    dst[i] = ((u64)hi << 32) | lo;
}

// ---------------------------------------------------------------------------
// Precompute dense rel-pos bias matrices (window-invariant).
// ---------------------------------------------------------------------------
__global__ void bias_kernel(const float* __restrict__ tb) {
    int i = blockIdx.x * blockDim.x + threadIdx.x;
    if (i >= 2*3*64*64) return;
    int layer = i / (3*4096);
    int r = i % (3*4096);
    int h = r / 4096;
    int qk = r & 4095;
    int q = qk >> 6, k = qk & 63;
    int qd = q >> 4, qh = (q >> 2) & 3, qw = q & 3;
    int kd = k >> 4, kh = (k >> 2) & 3, kw = k & 3;
    int ridx = (qd-kd+3)*49 + (qh-kh+3)*7 + (qw-kw+3);
    g_bias[i] = tb[layer*1029 + ridx*3 + h];
}

// ---------------------------------------------------------------------------
// Attention block, all GEMMs on tensor cores.
// One CTA per 4x4x4 window, 512 threads (16 warps: mt=warp&3, ng=warp>>2).
// ---------------------------------------------------------------------------
__global__ __launch_bounds__(512, 1) void attn_kernel(
    const float* __restrict__ x, float* __restrict__ out,
    const u64*  __restrict__ Wqkvf, const float* __restrict__ Bqkv,
    const u64*  __restrict__ Wpf,   const float* __restrict__ Bp,
    const float* __restrict__ biasM,
    const float* __restrict__ g1,   const float* __restrict__ b1,
    int shift)
{
    extern __shared__ float sm[];
    float* xw  = sm;                    // 64 x XW_LD; later aliased as ao
    float* qkv = xw + 64*XW_LD;         // 64 x 292 (tf32-rounded)
    float* S3  = qkv + 64*QKV_LD;       // 3 x 64 x 68
    float* ao  = xw;

    const int tid  = threadIdx.x;
    const int lane = tid & 31;
    const int warp = tid >> 5;
    const int mt   = warp & 3;
    const int ng   = warp >> 2;
    const int gid  = lane >> 2;
    const int tig  = lane & 3;

    const int bw   = blockIdx.x;
    const int b    = bw >> 12;
    const int widx = bw & 4095;
    const int wd   = widx >> 8;
    const int wh   = (widx >> 4) & 15;
    const int ww   = widx & 15;

    // ---- LN1 (one warp per token), store tf32-rounded ----
    for (int t = warp; t < 64; t += 16) {
        int td = t >> 4, th = (t >> 2) & 3, tw = t & 3;
        int gd = (wd*4 + td + shift) & 63;
        int gh = (wh*4 + th + shift) & 63;
        int gw = (ww*4 + tw + shift) & 63;
        const float* src = x + (size_t)((((b*64 + gd)*64 + gh)*64 + gw)) * 96;
        float v0 = src[lane], v1 = src[lane+32], v2 = src[lane+64];
        float s  = v0 + v1 + v2;
        float sq = v0*v0 + v1*v1 + v2*v2;
        #pragma unroll
        for (int o = 16; o; o >>= 1) {
            s  += __shfl_xor_sync(0xffffffffu, s,  o);
            sq += __shfl_xor_sync(0xffffffffu, sq, o);
        }
        float mean = s * (1.0f/96.0f);
        float var  = sq * (1.0f/96.0f) - mean*mean;
        float rstd = rsqrtf(var + 1e-5f);
        xw[t*XW_LD+lane]    = tf32r((v0-mean)*rstd*g1[lane]    + b1[lane]);
        xw[t*XW_LD+lane+32] = tf32r((v1-mean)*rstd*g1[lane+32] + b1[lane+32]);
        xw[t*XW_LD+lane+64] = tf32r((v2-mean)*rstd*g1[lane+64] + b1[lane+64]);
    }
    __syncthreads();

    // ---- QKV GEMM (MMA): 9 n-tiles per warp; outputs tf32-rounded, q scaled ----
    {
        float acc[9][4];
        #pragma unroll
        for (int nt = 0; nt < 9; nt++) {
            int col0 = 72*ng + 8*nt + 2*tig;
            float2 bb = *(const float2*)&Bqkv[col0];
            acc[nt][0] = bb.x; acc[nt][1] = bb.y;
            acc[nt][2] = bb.x; acc[nt][3] = bb.y;
        }
        #pragma unroll
        for (int kt = 0; kt < 12; kt++) {
            const float* arow0 = &xw[(16*mt + gid)*XW_LD + 8*kt];
            const float* arow1 = arow0 + 8*XW_LD;
            u32 a0 = __float_as_uint(arow0[tig]);
            u32 a1 = __float_as_uint(arow1[tig]);
            u32 a2 = __float_as_uint(arow0[tig+4]);
            u32 a3 = __float_as_uint(arow1[tig+4]);
            #pragma unroll
            for (int nt = 0; nt < 9; nt++) {
                u64 w = Wqkvf[(kt*36 + ng*9 + nt)*32 + lane];
                mma_tf32(acc[nt][0], acc[nt][1], acc[nt][2], acc[nt][3],
                         a0, a1, a2, a3, (u32)w, (u32)(w >> 32));
            }
        }
        const float qs = 0.17677669529663687f;  // 32^-0.5
        #pragma unroll
        for (int nt = 0; nt < 9; nt++) {
            int col0 = 72*ng + 8*nt + 2*tig;
            float sc = (72*ng + 8*nt < 96) ? qs : 1.0f;
            *(float2*)&qkv[(16*mt + gid)*QKV_LD + col0] =
                make_float2(tf32r(acc[nt][0]*sc), tf32r(acc[nt][1]*sc));
            *(float2*)&qkv[(16*mt + gid + 8)*QKV_LD + col0] =
                make_float2(tf32r(acc[nt][2]*sc), tf32r(acc[nt][3]*sc));
        }
    }
    __syncthreads();

    // ---- S = qK^T + bias (MMA): per head, ng covers 16 cols (2 n-tiles) ----
    #pragma unroll
    for (int h = 0; h < 3; h++) {
        float acc[2][4];
        #pragma unroll
        for (int j = 0; j < 2; j++)
            acc[j][0] = acc[j][1] = acc[j][2] = acc[j][3] = 0.f;
        #pragma unroll
        for (int ks = 0; ks < 4; ks++) {
            const float* ap = &qkv[(16*mt + gid)*QKV_LD + h*32 + 8*ks];
            u32 a0 = __float_as_uint(ap[tig]);
            u32 a1 = __float_as_uint(ap[8*QKV_LD + tig]);
            u32 a2 = __float_as_uint(ap[tig+4]);
            u32 a3 = __float_as_uint(ap[8*QKV_LD + tig+4]);
            #pragma unroll
            for (int j = 0; j < 2; j++) {
                const float* bp = &qkv[(ng*16 + j*8 + gid)*QKV_LD + 96 + h*32 + 8*ks];
                u32 b0 = __float_as_uint(bp[tig]);
                u32 b1 = __float_as_uint(bp[tig+4]);
                mma_tf32(acc[j][0], acc[j][1], acc[j][2], acc[j][3],
                         a0, a1, a2, a3, b0, b1);
            }
        }
        const float* bh = biasM + h*4096;
        #pragma unroll
        for (int j = 0; j < 2; j++) {
            int col = ng*16 + j*8 + 2*tig;
            int q0  = 16*mt + gid;
            float2 bb0 = *(const float2*)&bh[q0*64 + col];
            float2 bb1 = *(const float2*)&bh[(q0+8)*64 + col];
            *(float2*)&S3[(h*64 + q0)*S_LD + col] =
                make_float2(acc[j][0] + bb0.x, acc[j][1] + bb0.y);
            *(float2*)&S3[(h*64 + q0 + 8)*S_LD + col] =
                make_float2(acc[j][2] + bb1.x, acc[j][3] + bb1.y);
        }
    }
    __syncthreads();

    // ---- softmax: 8 lanes per row, all heads; probs tf32-rounded ----
    {
        int row = tid >> 3, sub = tid & 7;
        #pragma unroll
        for (int h = 0; h < 3; h++) {
            float* Sr = &S3[(h*64 + row)*S_LD + sub*8];
            float4 v0 = *(float4*)Sr;
            float4 v1 = *(float4*)(Sr + 4);
            float vals[8] = {v0.x,v0.y,v0.z,v0.w, v1.x,v1.y,v1.z,v1.w};
            float m = vals[0];
            #pragma unroll
            for (int c = 1; c < 8; c++) m = fmaxf(m, vals[c]);
            m = fmaxf(m, __shfl_xor_sync(0xffffffffu, m, 1));
            m = fmaxf(m, __shfl_xor_sync(0xffffffffu, m, 2));
            m = fmaxf(m, __shfl_xor_sync(0xffffffffu, m, 4));
            float ssum = 0.f;
            #pragma unroll
            for (int c = 0; c < 8; c++) { vals[c] = __expf(vals[c] - m); ssum += vals[c]; }
            ssum += __shfl_xor_sync(0xffffffffu, ssum, 1);
            ssum += __shfl_xor_sync(0xffffffffu, ssum, 2);
            ssum += __shfl_xor_sync(0xffffffffu, ssum, 4);
            float inv = 1.0f / ssum;
            *(float4*)Sr = make_float4(tf32r(vals[0]*inv), tf32r(vals[1]*inv),
                                       tf32r(vals[2]*inv), tf32r(vals[3]*inv));
            *(float4*)(Sr+4) = make_float4(tf32r(vals[4]*inv), tf32r(vals[5]*inv),
                                           tf32r(vals[6]*inv), tf32r(vals[7]*inv));
        }
    }
    __syncthreads();

    // ---- P@V (MMA): output 64x96, ng covers 24 cols (3 n-tiles) ----
    {
        float acc[3][4];
        #pragma unroll
        for (int j = 0; j < 3; j++)
            acc[j][0] = acc[j][1] = acc[j][2] = acc[j][3] = 0.f;
        #pragma unroll
        for (int j = 0; j < 3; j++) {
            int ct = ng*24 + j*8;
            int h  = ct >> 5;
            int dc = ct & 31;
            #pragma unroll
            for (int ks = 0; ks < 8; ks++) {
                const float* ap = &S3[(h*64 + 16*mt + gid)*S_LD + 8*ks];
                u32 a0 = __float_as_uint(ap[tig]);
                u32 a1 = __float_as_uint(ap[8*S_LD + tig]);
                u32 a2 = __float_as_uint(ap[tig+4]);
                u32 a3 = __float_as_uint(ap[8*S_LD + tig+4]);
                const float* bp = &qkv[(8*ks + tig)*QKV_LD + 192 + h*32 + dc + gid];
                u32 b0 = __float_as_uint(bp[0]);
                u32 b1 = __float_as_uint(bp[4*QKV_LD]);
                mma_tf32(acc[j][0], acc[j][1], acc[j][2], acc[j][3],
                         a0, a1, a2, a3, b0, b1);
            }
        }
        __syncthreads();   // xw/ao alias: ensure no one still needs xw (dead) / ordering
        #pragma unroll
        for (int j = 0; j < 3; j++) {
            int ct = ng*24 + j*8 + 2*tig;
            *(float2*)&ao[(16*mt + gid)*XW_LD + ct] =
                make_float2(tf32r(acc[j][0]), tf32r(acc[j][1]));
            *(float2*)&ao[(16*mt + gid + 8)*XW_LD + ct] =
                make_float2(tf32r(acc[j][2]), tf32r(acc[j][3]));
        }
    }
    __syncthreads();

    // ---- proj (MMA) + bias + residual -> global (shifted) ----
    {
        float acc[3][4];
        #pragma unroll
        for (int j = 0; j < 3; j++)
            acc[j][0] = acc[j][1] = acc[j][2] = acc[j][3] = 0.f;
        #pragma unroll
        for (int kt = 0; kt < 12; kt++) {
            const float* ap = &ao[(16*mt + gid)*XW_LD + 8*kt];
            u32 a0 = __float_as_uint(ap[tig]);
            u32 a1 = __float_as_uint(ap[8*XW_LD + tig]);
            u32 a2 = __float_as_uint(ap[tig+4]);
            u32 a3 = __float_as_uint(ap[8*XW_LD + tig+4]);
            #pragma unroll
            for (int j = 0; j < 3; j++) {
                u64 w = Wpf[(kt*12 + ng*3 + j)*32 + lane];
                mma_tf32(acc[j][0], acc[j][1], acc[j][2], acc[j][3],
                         a0, a1, a2, a3, (u32)w, (u32)(w >> 32));
            }
        }
        // epilogue: two rows per fragment
        int q0 = 16*mt + gid;
        #pragma unroll
        for (int rr = 0; rr < 2; rr++) {
            int t = q0 + 8*rr;
            int td = t >> 4, th = (t >> 2) & 3, tw = t & 3;
            int gd = (wd*4 + td + shift) & 63;
            int gh = (wh*4 + th + shift) & 63;
            int gw = (ww*4 + tw + shift) & 63;
            size_t idx = (size_t)((((b*64 + gd)*64 + gh)*64 + gw)) * 96;
            const float* rx = x + idx;
            float* dst = out + idx;
            #pragma unroll
            for (int j = 0; j < 3; j++) {
                int ct = ng*24 + j*8 + 2*tig;
                float2 bb = *(const float2*)&Bp[ct];
                float2 rv = *(const float2*)&rx[ct];
                *(float2*)&dst[ct] = make_float2(
                    acc[j][2*rr]   + bb.x + rv.x,
                    acc[j][2*rr+1] + bb.y + rv.y);
            }
        }
    }
}

// ---------------------------------------------------------------------------
// MLP block (unchanged from R7): LN2 -> GEMM1(MMA) -> GELU -> GEMM2(MMA)
// ---------------------------------------------------------------------------
__global__ __launch_bounds__(512, 1) void mlp_kernel(
    float* __restrict__ xa,
    const float* __restrict__ g2, const float* __restrict__ b2ln,
    const u64*  __restrict__ W1f, const float* __restrict__ B1,
    const u64*  __restrict__ W2f, const float* __restrict__ B2)
{
    extern __shared__ float sm[];
    float* y  = sm;             // 64 x XW_LD
    float* hb = y + 64*XW_LD;   // 64 x HB_LD

    const int tid  = threadIdx.x;
    const int lane = tid & 31;
    const int warp = tid >> 5;
    const size_t base = (size_t)blockIdx.x * 64;

    const int mt = warp & 3, ng = warp >> 2;
    const int gid = lane >> 2, tig = lane & 3;

    for (int t = warp; t < 64; t += 16) {
        const float* src = xa + (base + t) * 96;
        float v0 = src[lane], v1 = src[lane+32], v2 = src[lane+64];
        float s  = v0 + v1 + v2;
        float sq = v0*v0 + v1*v1 + v2*v2;
        #pragma unroll
        for (int o = 16; o; o >>= 1) {
            s  += __shfl_xor_sync(0xffffffffu, s,  o);
            sq += __shfl_xor_sync(0xffffffffu, sq, o);
        }
        float mean = s * (1.0f/96.0f);
        float var  = sq * (1.0f/96.0f) - mean*mean;
        float rstd = rsqrtf(var + 1e-5f);
        y[t*XW_LD+lane]    = tf32r((v0-mean)*rstd*g2[lane]    + b2ln[lane]);
        y[t*XW_LD+lane+32] = tf32r((v1-mean)*rstd*g2[lane+32] + b2ln[lane+32]);
        y[t*XW_LD+lane+64] = tf32r((v2-mean)*rstd*g2[lane+64] + b2ln[lane+64]);
    }
    __syncthreads();

    {
        float acc[12][4];
        #pragma unroll
        for (int nt = 0; nt < 12; nt++)
            acc[nt][0] = acc[nt][1] = acc[nt][2] = acc[nt][3] = 0.f;
        #pragma unroll
        for (int kt = 0; kt < 12; kt++) {
            const float* arow0 = &y[(16*mt + gid)*XW_LD + 8*kt];
            const float* arow1 = arow0 + 8*XW_LD;
            u32 a0 = __float_as_uint(arow0[tig]);
            u32 a1 = __float_as_uint(arow1[tig]);
            u32 a2 = __float_as_uint(arow0[tig+4]);
            u32 a3 = __float_as_uint(arow1[tig+4]);
            #pragma unroll
            for (int nt = 0; nt < 12; nt++) {
                u64 w = W1f[(kt*48 + ng*12 + nt)*32 + lane];
                mma_tf32(acc[nt][0], acc[nt][1], acc[nt][2], acc[nt][3],
                         a0, a1, a2, a3, (u32)w, (u32)(w >> 32));
            }
        }
        #pragma unroll
        for (int nt = 0; nt < 12; nt++) {
            int col0 = 96*ng + 8*nt + 2*tig;
            float2 bb = *(const float2*)&B1[col0];
            float u0 = acc[nt][0] + bb.x, u1 = acc[nt][1] + bb.y;
            float u2 = acc[nt][2] + bb.x, u3 = acc[nt][3] + bb.y;
            float g0 = 0.5f*u0*(1.0f + erff(u0*0.70710678118654752f));
            float g1v= 0.5f*u1*(1.0f + erff(u1*0.70710678118654752f));
            float g2v= 0.5f*u2*(1.0f + erff(u2*0.70710678118654752f));
            float g3 = 0.5f*u3*(1.0f + erff(u3*0.70710678118654752f));
            *(float2*)&hb[(16*mt + gid)*HB_LD + col0]     = make_float2(tf32r(g0), tf32r(g1v));
            *(float2*)&hb[(16*mt + gid + 8)*HB_LD + col0] = make_float2(tf32r(g2v), tf32r(g3));
        }
    }
    __syncthreads();

    {
        float acc[3][4];
        #pragma unroll
        for (int nt = 0; nt < 3; nt++)
            acc[nt][0] = acc[nt][1] = acc[nt][2] = acc[nt][3] = 0.f;
        #pragma unroll
        for (int kt = 0; kt < 48; kt++) {
            const float* arow0 = &hb[(16*mt + gid)*HB_LD + 8*kt];
            const float* arow1 = arow0 + 8*HB_LD;
            u32 a0 = __float_as_uint(arow0[tig]);
            u32 a1 = __float_as_uint(arow1[tig]);
            u32 a2 = __float_as_uint(arow0[tig+4]);
            u32 a3 = __float_as_uint(arow1[tig+4]);
            #pragma unroll
            for (int nt = 0; nt < 3; nt++) {
                u64 w = W2f[(kt*12 + ng*3 + nt)*32 + lane];
                mma_tf32(acc[nt][0], acc[nt][1], acc[nt][2], acc[nt][3],
                         a0, a1, a2, a3, (u32)w, (u32)(w >> 32));
            }
        }
        #pragma unroll
        for (int nt = 0; nt < 3; nt++) {
            int col0 = 24*ng + 8*nt + 2*tig;
            float2 bb = *(const float2*)&B2[col0];
            float* p0 = xa + (base + 16*mt + gid) * 96 + col0;
            float* p1 = xa + (base + 16*mt + gid + 8) * 96 + col0;
            float2 r0 = *(float2*)p0;
            float2 r1 = *(float2*)p1;
            *(float2*)p0 = make_float2(acc[nt][0] + bb.x + r0.x, acc[nt][1] + bb.y + r0.y);
            *(float2*)p1 = make_float2(acc[nt][2] + bb.x + r1.x, acc[nt][3] + bb.y + r1.y);
        }
    }
}

// ---------------------------------------------------------------------------
extern "C" void kernel_launch(void* const* d_in, const int* in_sizes, int n_in,
                              void* d_out, int out_size)
{
    const float* x      = (const float*)d_in[0];
    const float* qkv_w  = (const float*)d_in[1];
    const float* qkv_b  = (const float*)d_in[2];
    const float* proj_w = (const float*)d_in[3];
    const float* proj_b = (const float*)d_in[4];
    const float* btab   = (const float*)d_in[5];
    const float* ln1g   = (const float*)d_in[6];
    const float* ln1b   = (const float*)d_in[7];
    const float* ln2g   = (const float*)d_in[8];
    const float* ln2b   = (const float*)d_in[9];
    const float* w1     = (const float*)d_in[10];
    const float* b1     = (const float*)d_in[11];
    const float* w2     = (const float*)d_in[12];
    const float* b2     = (const float*)d_in[13];
    float* out = (float*)d_out;

    float* scratch = nullptr;
    u64 *wqkvf = nullptr, *w1f = nullptr, *w2f = nullptr, *wpf = nullptr;
    float* biasm = nullptr;
    cudaGetSymbolAddress((void**)&scratch, g_scratch);
    cudaGetSymbolAddress((void**)&wqkvf,   g_wqkvf);
    cudaGetSymbolAddress((void**)&w1f,     g_w1f);
    cudaGetSymbolAddress((void**)&w2f,     g_w2f);
    cudaGetSymbolAddress((void**)&wpf,     g_wpf);
    cudaGetSymbolAddress((void**)&biasm,   g_bias);

    cudaFuncSetAttribute(attn_kernel, cudaFuncAttributeMaxDynamicSharedMemorySize, ASMEM);
    cudaFuncSetAttribute(mlp_kernel,  cudaFuncAttributeMaxDynamicSharedMemorySize, MSMEM);

    // Prep: fragment-pack weights + dense bias matrices
    {
        int tq = 2*12*36*32, t1 = 2*12*48*32, t2 = 2*48*12*32, tp = 2*12*12*32;
        pack_kernel<<<(tq+255)/256, 256>>>(qkv_w, wqkvf, 12, 36, 288, tq);
        pack_kernel<<<(t1+255)/256, 256>>>(w1,    w1f,   12, 48, 384, t1);
        pack_kernel<<<(t2+255)/256, 256>>>(w2,    w2f,   48, 12,  96, t2);
        pack_kernel<<<(tp+255)/256, 256>>>(proj_w, wpf,  12, 12,  96, tp);
        bias_kernel<<<(2*3*64*64+255)/256, 256>>>(btab);
    }

    // ---- block 0 (shift 0) ----
    attn_kernel<<<NWIN, 512, ASMEM>>>(x, scratch,
        wqkvf, qkv_b, wpf, proj_b, biasm, ln1g, ln1b, 0);
    mlp_kernel<<<TOKENS/64, 512, MSMEM>>>(scratch,
        ln2g, ln2b, w1f, b1, w2f, b2);

    // ---- block 1 (shift 2) ----
    attn_kernel<<<NWIN, 512, ASMEM>>>(scratch, out,
        wqkvf + 12*36*32, qkv_b + 288, wpf + 12*12*32, proj_b + 96,
        biasm + 3*64*64, ln1g + 96, ln1b + 96, 2);
    mlp_kernel<<<TOKENS/64, 512, MSMEM>>>(out,
        ln2g + 96, ln2b + 96, w1f + 12*48*32, b1 + 384, w2f + 48*12*32, b2 + 96);
}